// round 13
// baseline (speedup 1.0000x reference)
#include <cuda_runtime.h>
#include <cuda_bf16.h>
#include <cstdint>

#define N_NODES 100000
#define N_EDGES 1600000
#define D 128
#define N_LAYERS 4
#define N_GRAPHS 512

// ---------------- device scratch ----------------
__device__ __nv_bfloat16 g_xwb[N_NODES * D];   // XW bf16 (25.6 MB)
__device__ float g_h[N_NODES * D];             // aggregated hidden fp32 (51.2 MB)
__device__ float g_dinv[N_NODES];
__device__ int   g_cnt[N_NODES];
__device__ int   g_rowptr[N_NODES + 1];
__device__ int   g_cursor[N_NODES];
__device__ int   g_bsum[512];
__device__ int   g_src[N_EDGES];
__device__ uint4 g_wpack[N_LAYERS * 4096];

// ---------------- CSR build ----------------
__global__ void zero_cnt_kernel() {
    int i = blockIdx.x * blockDim.x + threadIdx.x;
    if (i < N_NODES) g_cnt[i] = 0;
}

__device__ __forceinline__ int clampi(int v, int hi) {
    return v < 0 ? 0 : (v >= hi ? hi - 1 : v);
}

__global__ void count_kernel(const int4* __restrict__ col4) {
    int e = blockIdx.x * blockDim.x + threadIdx.x;
    if (e < N_EDGES / 4) {
        int4 c = col4[e];
        atomicAdd(&g_cnt[clampi(c.x, N_NODES)], 1);
        atomicAdd(&g_cnt[clampi(c.y, N_NODES)], 1);
        atomicAdd(&g_cnt[clampi(c.z, N_NODES)], 1);
        atomicAdd(&g_cnt[clampi(c.w, N_NODES)], 1);
    }
}

__global__ void scan1_kernel() {
    __shared__ int s[256];
    int t = threadIdx.x;
    int i = blockIdx.x * 256 + t;
    int v = (i < N_NODES) ? g_cnt[i] : 0;
    s[t] = v;
    __syncthreads();
    #pragma unroll
    for (int off = 1; off < 256; off <<= 1) {
        int add = (t >= off) ? s[t - off] : 0;
        __syncthreads();
        s[t] += add;
        __syncthreads();
    }
    if (i < N_NODES) g_rowptr[i] = s[t] - v;
    if (t == 255) g_bsum[blockIdx.x] = s[255];
}

__global__ void scan2_kernel(int nblocks) {
    __shared__ int s[512];
    int t = threadIdx.x;
    int v = (t < nblocks) ? g_bsum[t] : 0;
    s[t] = v;
    __syncthreads();
    #pragma unroll
    for (int off = 1; off < 512; off <<= 1) {
        int add = (t >= off) ? s[t - off] : 0;
        __syncthreads();
        s[t] += add;
        __syncthreads();
    }
    if (t < nblocks) g_bsum[t] = s[t] - v;
}

__global__ void scan3_kernel() {
    int i = blockIdx.x * 256 + threadIdx.x;
    if (i < N_NODES) {
        int rp = g_rowptr[i] + g_bsum[blockIdx.x];
        g_rowptr[i] = rp;
        g_cursor[i] = rp;
        g_dinv[i] = rsqrtf((float)(g_cnt[i] + 1));
    }
    if (i == 0) g_rowptr[N_NODES] = N_EDGES;
}

__global__ void fill_kernel(const int4* __restrict__ row4, const int4* __restrict__ col4) {
    int e = blockIdx.x * blockDim.x + threadIdx.x;
    if (e < N_EDGES / 4) {
        int4 r = row4[e];
        int4 c = col4[e];
        int p;
        p = atomicAdd(&g_cursor[clampi(c.x, N_NODES)], 1);
        if (p >= 0 && p < N_EDGES) g_src[p] = clampi(r.x, N_NODES);
        p = atomicAdd(&g_cursor[clampi(c.y, N_NODES)], 1);
        if (p >= 0 && p < N_EDGES) g_src[p] = clampi(r.y, N_NODES);
        p = atomicAdd(&g_cursor[clampi(c.z, N_NODES)], 1);
        if (p >= 0 && p < N_EDGES) g_src[p] = clampi(r.z, N_NODES);
        p = atomicAdd(&g_cursor[clampi(c.w, N_NODES)], 1);
        if (p >= 0 && p < N_EDGES) g_src[p] = clampi(r.w, N_NODES);
    }
}

// ---------------- W preprocessing ----------------
__device__ __forceinline__ uint32_t pack_bf16(float a, float b) {
    return (uint32_t)__bfloat16_as_ushort(__float2bfloat16_rn(a))
         | ((uint32_t)__bfloat16_as_ushort(__float2bfloat16_rn(b)) << 16);
}
__device__ __forceinline__ float bf16_res(float a) {
    return a - __bfloat162float(__float2bfloat16_rn(a));
}

__global__ void wsplit_kernel(const float* __restrict__ Ws) {
    int l = blockIdx.x;
    const float* W = Ws + l * D * D;
    for (int idx = threadIdx.x; idx < 4096; idx += blockDim.x) {
        int lane = idx & 31;
        int nt = (idx >> 5) & 15;
        int s = idx >> 9;
        int g = lane >> 2, tg = lane & 3;
        int n = nt * 8 + g;
        int ka = s * 16 + tg * 2;
        int kb = ka + 8;
        float w00 = W[ka * D + n], w01 = W[(ka + 1) * D + n];
        float w10 = W[kb * D + n], w11 = W[(kb + 1) * D + n];
        uint4 o;
        o.x = pack_bf16(w00, w01);
        o.y = pack_bf16(w10, w11);
        o.z = pack_bf16(bf16_res(w00), bf16_res(w01));
        o.w = pack_bf16(bf16_res(w10), bf16_res(w11));
        g_wpack[l * 4096 + idx] = o;
    }
}

// ---------------- Tensor-core GEMM (64-row tiles, 3 CTAs/SM, B via L1) ----------------
#define FRAG_STRIDE 528
#define SM_AHI 0
#define SM_ALO (SM_AHI + 32 * FRAG_STRIDE)
#define GEMM_SMEM (SM_ALO + 32 * FRAG_STRIDE)  // 33792

__device__ __forceinline__ void mma16816(float c[4], uint32_t a0, uint32_t a1, uint32_t a2,
                                         uint32_t a3, uint32_t b0, uint32_t b1) {
    asm volatile(
        "mma.sync.aligned.m16n8k16.row.col.f32.bf16.bf16.f32 "
        "{%0,%1,%2,%3}, {%4,%5,%6,%7}, {%8,%9}, {%0,%1,%2,%3};"
        : "+f"(c[0]), "+f"(c[1]), "+f"(c[2]), "+f"(c[3])
        : "r"(a0), "r"(a1), "r"(a2), "r"(a3), "r"(b0), "r"(b1));
}

__global__ void __launch_bounds__(256, 3)
gemm_mma_kernel(const float* __restrict__ A,
                const uint4* __restrict__ wpack,
                __nv_bfloat16* __restrict__ Cb) {
    extern __shared__ char smem[];
    int t = threadIdx.x;
    int warp = t >> 5, lane = t & 31;
    int m0 = blockIdx.x * 64;

    // ---- load A tile fp32 (64 rows), split hi/lo, store as packed fragments ----
    {
        const float4* A4 = (const float4*)A;
        #pragma unroll
        for (int i = 0; i < 8; i++) {
            int idx = i * 256 + t;
            int row = idx >> 5, q = idx & 31;
            float4 v = make_float4(0.f, 0.f, 0.f, 0.f);
            if (m0 + row < N_NODES) v = A4[(size_t)(m0 + row) * 32 + q];
            int rowin = row & 15, wb = row >> 4;
            int g = rowin & 7, hr = rowin >> 3;
            int s = q >> 2, rr = (q & 3) << 2;
            int tg0 = (rr & 4) ? 2 : 0;
            int sl = ((rr & 8) ? 2 : 0) + hr;
            int l0 = (g << 2) + tg0;
            int foff = (wb * 8 + s) * FRAG_STRIDE;
            *(uint32_t*)(smem + SM_AHI + foff + l0 * 16 + sl * 4) = pack_bf16(v.x, v.y);
            *(uint32_t*)(smem + SM_AHI + foff + (l0 + 1) * 16 + sl * 4) = pack_bf16(v.z, v.w);
            *(uint32_t*)(smem + SM_ALO + foff + l0 * 16 + sl * 4) =
                pack_bf16(bf16_res(v.x), bf16_res(v.y));
            *(uint32_t*)(smem + SM_ALO + foff + (l0 + 1) * 16 + sl * 4) =
                pack_bf16(bf16_res(v.z), bf16_res(v.w));
        }
    }
    __syncthreads();

    int rowblk = warp >> 1;
    int nthalf = warp & 1;
    int g = lane >> 2;
    int tg = lane & 3;

    float acc[8][4];
    #pragma unroll
    for (int nt = 0; nt < 8; nt++)
        #pragma unroll
        for (int j = 0; j < 4; j++) acc[nt][j] = 0.f;

    #pragma unroll
    for (int s = 0; s < 8; s++) {
        int foff = (rowblk * 8 + s) * FRAG_STRIDE + lane * 16;
        uint4 ha = *(const uint4*)(smem + SM_AHI + foff);
        uint4 la = *(const uint4*)(smem + SM_ALO + foff);
        const uint4* bp = wpack + s * 512 + (nthalf * 8) * 32 + lane;
        #pragma unroll
        for (int nt = 0; nt < 8; nt++) {
            uint4 bb = __ldg(bp + nt * 32);
            mma16816(acc[nt], ha.x, ha.y, ha.z, ha.w, bb.x, bb.y);
            mma16816(acc[nt], ha.x, ha.y, ha.z, ha.w, bb.z, bb.w);
            mma16816(acc[nt], la.x, la.y, la.z, la.w, bb.x, bb.y);
        }
    }

    int r0 = m0 + rowblk * 16 + g;
    int r1 = r0 + 8;
    #pragma unroll
    for (int nt = 0; nt < 8; nt++) {
        int cb = (nthalf * 8 + nt) * 8 + tg * 2;
        if (r0 < N_NODES)
            *(uint32_t*)&Cb[(size_t)r0 * D + cb] = pack_bf16(acc[nt][0], acc[nt][1]);
        if (r1 < N_NODES)
            *(uint32_t*)&Cb[(size_t)r1 * D + cb] = pack_bf16(acc[nt][2], acc[nt][3]);
    }
}

// ---------------- Aggregation v1 (REAL, warp/node) ----------------
__device__ __forceinline__ void acc_bf16w(float4& a, uint2 u, float w) {
    float f0 = __uint_as_float(u.x << 16);
    float f1 = __uint_as_float(u.x & 0xffff0000u);
    float f2 = __uint_as_float(u.y << 16);
    float f3 = __uint_as_float(u.y & 0xffff0000u);
    a.x = fmaf(w, f0, a.x); a.y = fmaf(w, f1, a.y);
    a.z = fmaf(w, f2, a.z); a.w = fmaf(w, f3, a.w);
}

__global__ void aggregate_kernel(const __nv_bfloat16* __restrict__ xwb,
                                 const float* __restrict__ bias,
                                 float* __restrict__ hout, int do_relu) {
    int gw = (blockIdx.x * blockDim.x + threadIdx.x) >> 5;
    int lane = threadIdx.x & 31;
    if (gw >= N_NODES) return;
    int v = gw;
    int beg = g_rowptr[v];
    int end = g_rowptr[v + 1];

    const uint2* xb = (const uint2*)xwb;
    float4 a0 = make_float4(0.f, 0.f, 0.f, 0.f);
    float4 a1 = make_float4(0.f, 0.f, 0.f, 0.f);
    float4 a2 = make_float4(0.f, 0.f, 0.f, 0.f);
    float4 a3 = make_float4(0.f, 0.f, 0.f, 0.f);

    for (int p = beg; p < end; p += 32) {
        int m = end - p; if (m > 32) m = 32;
        int sl = g_src[p + (lane < m ? lane : 0)];
        float dl = g_dinv[sl];
        int j = 0;
        for (; j + 4 <= m; j += 4) {
            int s0 = __shfl_sync(0xffffffffu, sl, j);
            int s1 = __shfl_sync(0xffffffffu, sl, j + 1);
            int s2 = __shfl_sync(0xffffffffu, sl, j + 2);
            int s3 = __shfl_sync(0xffffffffu, sl, j + 3);
            float w0 = __shfl_sync(0xffffffffu, dl, j);
            float w1 = __shfl_sync(0xffffffffu, dl, j + 1);
            float w2 = __shfl_sync(0xffffffffu, dl, j + 2);
            float w3 = __shfl_sync(0xffffffffu, dl, j + 3);
            uint2 u0 = xb[(size_t)s0 * 32 + lane];
            uint2 u1 = xb[(size_t)s1 * 32 + lane];
            uint2 u2 = xb[(size_t)s2 * 32 + lane];
            uint2 u3 = xb[(size_t)s3 * 32 + lane];
            acc_bf16w(a0, u0, w0);
            acc_bf16w(a1, u1, w1);
            acc_bf16w(a2, u2, w2);
            acc_bf16w(a3, u3, w3);
        }
        for (; j < m; j++) {
            int s0 = __shfl_sync(0xffffffffu, sl, j);
            float w0 = __shfl_sync(0xffffffffu, dl, j);
            uint2 u0 = xb[(size_t)s0 * 32 + lane];
            acc_bf16w(a0, u0, w0);
        }
    }

    float dv = g_dinv[v];
    uint2 us = xb[(size_t)v * 32 + lane];
    acc_bf16w(a0, us, dv);

    float4 b4 = ((const float4*)bias)[lane];
    float rx = dv * (a0.x + a1.x + a2.x + a3.x) + b4.x;
    float ry = dv * (a0.y + a1.y + a2.y + a3.y) + b4.y;
    float rz = dv * (a0.z + a1.z + a2.z + a3.z) + b4.z;
    float rw = dv * (a0.w + a1.w + a2.w + a3.w) + b4.w;

    if (do_relu) {
        rx = fmaxf(rx, 0.f); ry = fmaxf(ry, 0.f);
        rz = fmaxf(rz, 0.f); rw = fmaxf(rw, 0.f);
    }
    ((float4*)hout)[(size_t)v * 32 + lane] = make_float4(rx, ry, rz, rw);
}

// ---------------- Aggregation v2 (SANDBOX probe: 2 warps/node, 2x MLP) ----------------
// Runs BEFORE the real agg each layer; its g_h output is fully overwritten, so
// it only contributes measurable time.  Tests the latency-bound hypothesis.
__device__ __forceinline__ void acc_bf16w2(float2& a, uint32_t u, float w) {
    float f0 = __uint_as_float(u << 16);
    float f1 = __uint_as_float(u & 0xffff0000u);
    a.x = fmaf(w, f0, a.x);
    a.y = fmaf(w, f1, a.y);
}

__global__ void aggregate_v2_kernel(const __nv_bfloat16* __restrict__ xwb,
                                    const float* __restrict__ bias,
                                    float* __restrict__ hout, int do_relu) {
    int gw = (blockIdx.x * blockDim.x + threadIdx.x) >> 5;
    int lane = threadIdx.x & 31;
    int v = gw >> 1;
    int half = gw & 1;
    if (v >= N_NODES) return;
    int beg = g_rowptr[v];
    int end = g_rowptr[v + 1];

    const uint32_t* xb = (const uint32_t*)xwb;   // 64 u32 chunks/row
    int coff = half * 32 + lane;                 // u32 index within row
    float2 a0 = make_float2(0.f, 0.f);
    float2 a1 = make_float2(0.f, 0.f);
    float2 a2 = make_float2(0.f, 0.f);
    float2 a3 = make_float2(0.f, 0.f);

    for (int p = beg; p < end; p += 32) {
        int m = end - p; if (m > 32) m = 32;
        int sl = g_src[p + (lane < m ? lane : 0)];
        float dl = g_dinv[sl];
        int j = 0;
        for (; j + 4 <= m; j += 4) {
            int s0 = __shfl_sync(0xffffffffu, sl, j);
            int s1 = __shfl_sync(0xffffffffu, sl, j + 1);
            int s2 = __shfl_sync(0xffffffffu, sl, j + 2);
            int s3 = __shfl_sync(0xffffffffu, sl, j + 3);
            float w0 = __shfl_sync(0xffffffffu, dl, j);
            float w1 = __shfl_sync(0xffffffffu, dl, j + 1);
            float w2 = __shfl_sync(0xffffffffu, dl, j + 2);
            float w3 = __shfl_sync(0xffffffffu, dl, j + 3);
            uint32_t u0 = xb[(size_t)s0 * 64 + coff];
            uint32_t u1 = xb[(size_t)s1 * 64 + coff];
            uint32_t u2 = xb[(size_t)s2 * 64 + coff];
            uint32_t u3 = xb[(size_t)s3 * 64 + coff];
            acc_bf16w2(a0, u0, w0);
            acc_bf16w2(a1, u1, w1);
            acc_bf16w2(a2, u2, w2);
            acc_bf16w2(a3, u3, w3);
        }
        for (; j < m; j++) {
            int s0 = __shfl_sync(0xffffffffu, sl, j);
            float w0 = __shfl_sync(0xffffffffu, dl, j);
            uint32_t u0 = xb[(size_t)s0 * 64 + coff];
            acc_bf16w2(a0, u0, w0);
        }
    }

    float dv = g_dinv[v];
    uint32_t us = xb[(size_t)v * 64 + coff];
    acc_bf16w2(a0, us, dv);

    float2 b2 = ((const float2*)bias)[coff];
    float rx = dv * (a0.x + a1.x + a2.x + a3.x) + b2.x;
    float ry = dv * (a0.y + a1.y + a2.y + a3.y) + b2.y;
    if (do_relu) { rx = fmaxf(rx, 0.f); ry = fmaxf(ry, 0.f); }
    ((float2*)hout)[(size_t)v * 64 + coff] = make_float2(rx, ry);
}

// ---------------- Pool + MLP head ----------------
__global__ void pool_mlp_kernel(const float* __restrict__ h, const int* __restrict__ batch,
                                const float* __restrict__ w1, const float* __restrict__ b1,
                                const float* __restrict__ w2, const float* __restrict__ b2,
                                float* __restrict__ out) {
    int g = blockIdx.x;
    int t = threadIdx.x;

    __shared__ int s_bounds[2];
    if (t < 2) {
        int target = g + t;
        int lo = 0, hi = N_NODES;
        while (lo < hi) {
            int mid = (lo + hi) >> 1;
            if (batch[mid] < target) lo = mid + 1; else hi = mid;
        }
        s_bounds[t] = lo;
    }
    __syncthreads();
    int beg = s_bounds[0], end = s_bounds[1];

    float sum = 0.f;
    for (int n = beg; n < end; n++) sum += h[(size_t)n * D + t];
    float cnt = fmaxf((float)(end - beg), 1.0f);

    __shared__ float pooled[D];
    __shared__ float hid[100];
    pooled[t] = sum / cnt;
    __syncthreads();

    if (t < 100) {
        float a = b1[t];
        #pragma unroll 8
        for (int k = 0; k < D; k++) a += pooled[k] * w1[k * 100 + t];
        hid[t] = fmaxf(a, 0.f);
    }
    __syncthreads();

    if (t < 4) {
        float a = b2[t];
        #pragma unroll
        for (int k = 0; k < 100; k++) a += hid[k] * w2[k * 4 + t];
        out[g * 4 + t] = a;
    }
}

// ---------------- launch ----------------
extern "C" void kernel_launch(void* const* d_in, const int* in_sizes, int n_in,
                              void* d_out, int out_size) {
    const float *x = 0, *Ws = 0, *bs = 0, *w1 = 0, *b1 = 0, *w2 = 0, *b2 = 0;
    const int *eidx = 0, *batch = 0;
    for (int i = 0; i < n_in; i++) {
        switch (in_sizes[i]) {
            case 12800000: x     = (const float*)d_in[i]; break;
            case 65536:    Ws    = (const float*)d_in[i]; break;
            case 512:      bs    = (const float*)d_in[i]; break;
            case 12800:    w1    = (const float*)d_in[i]; break;
            case 100:      b1    = (const float*)d_in[i]; break;
            case 400:      w2    = (const float*)d_in[i]; break;
            case 4:        b2    = (const float*)d_in[i]; break;
            case 3200000:  eidx  = (const int*)d_in[i]; break;
            case 100000:   batch = (const int*)d_in[i]; break;
            default: break;
        }
    }
    float* out = (float*)d_out;

    const int* row = eidx;
    const int* col = eidx + N_EDGES;

    float *p_h = nullptr;
    __nv_bfloat16 *p_xwb = nullptr;
    uint4 *p_wpack = nullptr;
    cudaGetSymbolAddress((void**)&p_xwb,  g_xwb);
    cudaGetSymbolAddress((void**)&p_h,    g_h);
    cudaGetSymbolAddress((void**)&p_wpack, g_wpack);

    const int NB_NODE = (N_NODES + 255) / 256;
    const int NB_EDGE4 = (N_EDGES / 4 + 255) / 256;
    const int TC_BLOCKS = (N_NODES + 63) / 64;           // 1563
    const int AGG_BLOCKS = (N_NODES * 32 + 255) / 256;   // warp/node
    const int AGG2_BLOCKS = (N_NODES * 64 + 255) / 256;  // 2 warps/node

    cudaFuncSetAttribute(gemm_mma_kernel, cudaFuncAttributeMaxDynamicSharedMemorySize, GEMM_SMEM);

    // Order keeps layer-0 GEMM at in-stream index 3 (the ncu-captured slot).
    wsplit_kernel<<<N_LAYERS, 256>>>(Ws);                                   // [0]
    zero_cnt_kernel<<<NB_NODE, 256>>>();                                    // [1]
    count_kernel<<<NB_EDGE4, 256>>>((const int4*)col);                      // [2]
    gemm_mma_kernel<<<TC_BLOCKS, 256, GEMM_SMEM>>>(x, p_wpack, p_xwb);      // [3] <- PROFILED
    scan1_kernel<<<NB_NODE, 256>>>();                                       // [4]
    scan2_kernel<<<1, 512>>>(NB_NODE);                                      // [5]
    scan3_kernel<<<NB_NODE, 256>>>();                                       // [6]
    fill_kernel<<<NB_EDGE4, 256>>>((const int4*)row, (const int4*)col);     // [7]

    // sandbox v2 probe (output discarded) then real agg (overwrites g_h)
    aggregate_v2_kernel<<<AGG2_BLOCKS, 256>>>(p_xwb, bs, p_h, 1);
    aggregate_kernel<<<AGG_BLOCKS, 256>>>(p_xwb, bs, p_h, 1);
    const float* hin = p_h;
    for (int l = 1; l < N_LAYERS; l++) {
        gemm_mma_kernel<<<TC_BLOCKS, 256, GEMM_SMEM>>>(hin, p_wpack + (size_t)l * 4096, p_xwb);
        aggregate_v2_kernel<<<AGG2_BLOCKS, 256>>>(p_xwb, bs + (size_t)l * D, p_h,
                                                  (l < N_LAYERS - 1) ? 1 : 0);
        aggregate_kernel<<<AGG_BLOCKS, 256>>>(p_xwb, bs + (size_t)l * D, p_h,
                                              (l < N_LAYERS - 1) ? 1 : 0);
        hin = p_h;
    }

    pool_mlp_kernel<<<N_GRAPHS, 128>>>(p_h, batch, w1, b1, w2, b2, out);
}

// round 14
// speedup vs baseline: 1.5423x; 1.5423x over previous
#include <cuda_runtime.h>
#include <cuda_bf16.h>
#include <cstdint>

#define N_NODES 100000
#define N_EDGES 1600000
#define D 128
#define N_LAYERS 4
#define N_GRAPHS 512

// ---------------- device scratch ----------------
__device__ __nv_bfloat16 g_xwb[N_NODES * D];   // XW bf16 (25.6 MB)
__device__ float g_h[N_NODES * D];             // aggregated hidden fp32 (51.2 MB)
__device__ float g_dinv[N_NODES];
__device__ int   g_cnt[N_NODES];
__device__ int   g_rowptr[N_NODES + 1];
__device__ int   g_cursor[N_NODES];
__device__ int   g_bsum[512];
__device__ int   g_src[N_EDGES];
__device__ uint4 g_wpack[N_LAYERS * 4096];

// ---------------- CSR build ----------------
__global__ void zero_cnt_kernel() {
    int i = blockIdx.x * blockDim.x + threadIdx.x;
    if (i < N_NODES) g_cnt[i] = 0;
}

__device__ __forceinline__ int clampi(int v, int hi) {
    return v < 0 ? 0 : (v >= hi ? hi - 1 : v);
}

__global__ void count_kernel(const int4* __restrict__ col4) {
    int e = blockIdx.x * blockDim.x + threadIdx.x;
    if (e < N_EDGES / 4) {
        int4 c = col4[e];
        atomicAdd(&g_cnt[clampi(c.x, N_NODES)], 1);
        atomicAdd(&g_cnt[clampi(c.y, N_NODES)], 1);
        atomicAdd(&g_cnt[clampi(c.z, N_NODES)], 1);
        atomicAdd(&g_cnt[clampi(c.w, N_NODES)], 1);
    }
}

__global__ void scan1_kernel() {
    __shared__ int s[256];
    int t = threadIdx.x;
    int i = blockIdx.x * 256 + t;
    int v = (i < N_NODES) ? g_cnt[i] : 0;
    s[t] = v;
    __syncthreads();
    #pragma unroll
    for (int off = 1; off < 256; off <<= 1) {
        int add = (t >= off) ? s[t - off] : 0;
        __syncthreads();
        s[t] += add;
        __syncthreads();
    }
    if (i < N_NODES) g_rowptr[i] = s[t] - v;
    if (t == 255) g_bsum[blockIdx.x] = s[255];
}

__global__ void scan2_kernel(int nblocks) {
    __shared__ int s[512];
    int t = threadIdx.x;
    int v = (t < nblocks) ? g_bsum[t] : 0;
    s[t] = v;
    __syncthreads();
    #pragma unroll
    for (int off = 1; off < 512; off <<= 1) {
        int add = (t >= off) ? s[t - off] : 0;
        __syncthreads();
        s[t] += add;
        __syncthreads();
    }
    if (t < nblocks) g_bsum[t] = s[t] - v;
}

__global__ void scan3_kernel() {
    int i = blockIdx.x * 256 + threadIdx.x;
    if (i < N_NODES) {
        int rp = g_rowptr[i] + g_bsum[blockIdx.x];
        g_rowptr[i] = rp;
        g_cursor[i] = rp;
        g_dinv[i] = rsqrtf((float)(g_cnt[i] + 1));
    }
    if (i == 0) g_rowptr[N_NODES] = N_EDGES;
}

__global__ void fill_kernel(const int4* __restrict__ row4, const int4* __restrict__ col4) {
    int e = blockIdx.x * blockDim.x + threadIdx.x;
    if (e < N_EDGES / 4) {
        int4 r = row4[e];
        int4 c = col4[e];
        int p;
        p = atomicAdd(&g_cursor[clampi(c.x, N_NODES)], 1);
        if (p >= 0 && p < N_EDGES) g_src[p] = clampi(r.x, N_NODES);
        p = atomicAdd(&g_cursor[clampi(c.y, N_NODES)], 1);
        if (p >= 0 && p < N_EDGES) g_src[p] = clampi(r.y, N_NODES);
        p = atomicAdd(&g_cursor[clampi(c.z, N_NODES)], 1);
        if (p >= 0 && p < N_EDGES) g_src[p] = clampi(r.z, N_NODES);
        p = atomicAdd(&g_cursor[clampi(c.w, N_NODES)], 1);
        if (p >= 0 && p < N_EDGES) g_src[p] = clampi(r.w, N_NODES);
    }
}

// ---------------- W preprocessing ----------------
__device__ __forceinline__ uint32_t pack_bf16(float a, float b) {
    return (uint32_t)__bfloat16_as_ushort(__float2bfloat16_rn(a))
         | ((uint32_t)__bfloat16_as_ushort(__float2bfloat16_rn(b)) << 16);
}
__device__ __forceinline__ float bf16_res(float a) {
    return a - __bfloat162float(__float2bfloat16_rn(a));
}

__global__ void wsplit_kernel(const float* __restrict__ Ws) {
    int l = blockIdx.x;
    const float* W = Ws + l * D * D;
    for (int idx = threadIdx.x; idx < 4096; idx += blockDim.x) {
        int lane = idx & 31;
        int nt = (idx >> 5) & 15;
        int s = idx >> 9;
        int g = lane >> 2, tg = lane & 3;
        int n = nt * 8 + g;
        int ka = s * 16 + tg * 2;
        int kb = ka + 8;
        float w00 = W[ka * D + n], w01 = W[(ka + 1) * D + n];
        float w10 = W[kb * D + n], w11 = W[(kb + 1) * D + n];
        uint4 o;
        o.x = pack_bf16(w00, w01);
        o.y = pack_bf16(w10, w11);
        o.z = pack_bf16(bf16_res(w00), bf16_res(w01));
        o.w = pack_bf16(bf16_res(w10), bf16_res(w11));
        g_wpack[l * 4096 + idx] = o;
    }
}

// ---------------- Tensor-core GEMM (64-row tiles, 2 CTAs/SM, B via L1) ----------------
#define FRAG_STRIDE 528
#define SM_AHI 0
#define SM_ALO (SM_AHI + 32 * FRAG_STRIDE)
#define GEMM_SMEM (SM_ALO + 32 * FRAG_STRIDE)  // 33792

__device__ __forceinline__ void mma16816(float c[4], uint32_t a0, uint32_t a1, uint32_t a2,
                                         uint32_t a3, uint32_t b0, uint32_t b1) {
    asm volatile(
        "mma.sync.aligned.m16n8k16.row.col.f32.bf16.bf16.f32 "
        "{%0,%1,%2,%3}, {%4,%5,%6,%7}, {%8,%9}, {%0,%1,%2,%3};"
        : "+f"(c[0]), "+f"(c[1]), "+f"(c[2]), "+f"(c[3])
        : "r"(a0), "r"(a1), "r"(a2), "r"(a3), "r"(b0), "r"(b1));
}

__global__ void __launch_bounds__(256, 2)
gemm_mma_kernel(const float* __restrict__ A,
                const uint4* __restrict__ wpack,
                __nv_bfloat16* __restrict__ Cb) {
    extern __shared__ char smem[];
    int t = threadIdx.x;
    int warp = t >> 5, lane = t & 31;
    int m0 = blockIdx.x * 64;

    {
        const float4* A4 = (const float4*)A;
        #pragma unroll
        for (int i = 0; i < 8; i++) {
            int idx = i * 256 + t;
            int row = idx >> 5, q = idx & 31;
            float4 v = make_float4(0.f, 0.f, 0.f, 0.f);
            if (m0 + row < N_NODES) v = A4[(size_t)(m0 + row) * 32 + q];
            int rowin = row & 15, wb = row >> 4;
            int g = rowin & 7, hr = rowin >> 3;
            int s = q >> 2, rr = (q & 3) << 2;
            int tg0 = (rr & 4) ? 2 : 0;
            int sl = ((rr & 8) ? 2 : 0) + hr;
            int l0 = (g << 2) + tg0;
            int foff = (wb * 8 + s) * FRAG_STRIDE;
            *(uint32_t*)(smem + SM_AHI + foff + l0 * 16 + sl * 4) = pack_bf16(v.x, v.y);
            *(uint32_t*)(smem + SM_AHI + foff + (l0 + 1) * 16 + sl * 4) = pack_bf16(v.z, v.w);
            *(uint32_t*)(smem + SM_ALO + foff + l0 * 16 + sl * 4) =
                pack_bf16(bf16_res(v.x), bf16_res(v.y));
            *(uint32_t*)(smem + SM_ALO + foff + (l0 + 1) * 16 + sl * 4) =
                pack_bf16(bf16_res(v.z), bf16_res(v.w));
        }
    }
    __syncthreads();

    int rowblk = warp >> 1;
    int nthalf = warp & 1;
    int g = lane >> 2;
    int tg = lane & 3;

    float acc[8][4];
    #pragma unroll
    for (int nt = 0; nt < 8; nt++)
        #pragma unroll
        for (int j = 0; j < 4; j++) acc[nt][j] = 0.f;

    #pragma unroll
    for (int s = 0; s < 8; s++) {
        int foff = (rowblk * 8 + s) * FRAG_STRIDE + lane * 16;
        uint4 ha = *(const uint4*)(smem + SM_AHI + foff);
        uint4 la = *(const uint4*)(smem + SM_ALO + foff);
        const uint4* bp = wpack + s * 512 + (nthalf * 8) * 32 + lane;
        #pragma unroll
        for (int nt = 0; nt < 8; nt++) {
            uint4 bb = __ldg(bp + nt * 32);
            mma16816(acc[nt], ha.x, ha.y, ha.z, ha.w, bb.x, bb.y);
            mma16816(acc[nt], ha.x, ha.y, ha.z, ha.w, bb.z, bb.w);
            mma16816(acc[nt], la.x, la.y, la.z, la.w, bb.x, bb.y);
        }
    }

    int r0 = m0 + rowblk * 16 + g;
    int r1 = r0 + 8;
    #pragma unroll
    for (int nt = 0; nt < 8; nt++) {
        int cb = (nthalf * 8 + nt) * 8 + tg * 2;
        if (r0 < N_NODES)
            *(uint32_t*)&Cb[(size_t)r0 * D + cb] = pack_bf16(acc[nt][0], acc[nt][1]);
        if (r1 < N_NODES)
            *(uint32_t*)&Cb[(size_t)r1 * D + cb] = pack_bf16(acc[nt][2], acc[nt][3]);
    }
}

// ---------------- Aggregation (warp/node, bf16 gather) ----------------
__device__ __forceinline__ void acc_bf16w(float4& a, uint2 u, float w) {
    float f0 = __uint_as_float(u.x << 16);
    float f1 = __uint_as_float(u.x & 0xffff0000u);
    float f2 = __uint_as_float(u.y << 16);
    float f3 = __uint_as_float(u.y & 0xffff0000u);
    a.x = fmaf(w, f0, a.x); a.y = fmaf(w, f1, a.y);
    a.z = fmaf(w, f2, a.z); a.w = fmaf(w, f3, a.w);
}

__global__ void aggregate_kernel(const __nv_bfloat16* __restrict__ xwb,
                                 const float* __restrict__ bias,
                                 float* __restrict__ hout, int do_relu) {
    int gw = (blockIdx.x * blockDim.x + threadIdx.x) >> 5;
    int lane = threadIdx.x & 31;
    if (gw >= N_NODES) return;
    int v = gw;
    int beg = g_rowptr[v];
    int end = g_rowptr[v + 1];

    const uint2* xb = (const uint2*)xwb;
    float4 a0 = make_float4(0.f, 0.f, 0.f, 0.f);
    float4 a1 = make_float4(0.f, 0.f, 0.f, 0.f);
    float4 a2 = make_float4(0.f, 0.f, 0.f, 0.f);
    float4 a3 = make_float4(0.f, 0.f, 0.f, 0.f);

    for (int p = beg; p < end; p += 32) {
        int m = end - p; if (m > 32) m = 32;
        int sl = g_src[p + (lane < m ? lane : 0)];
        float dl = g_dinv[sl];
        int j = 0;
        for (; j + 4 <= m; j += 4) {
            int s0 = __shfl_sync(0xffffffffu, sl, j);
            int s1 = __shfl_sync(0xffffffffu, sl, j + 1);
            int s2 = __shfl_sync(0xffffffffu, sl, j + 2);
            int s3 = __shfl_sync(0xffffffffu, sl, j + 3);
            float w0 = __shfl_sync(0xffffffffu, dl, j);
            float w1 = __shfl_sync(0xffffffffu, dl, j + 1);
            float w2 = __shfl_sync(0xffffffffu, dl, j + 2);
            float w3 = __shfl_sync(0xffffffffu, dl, j + 3);
            uint2 u0 = xb[(size_t)s0 * 32 + lane];
            uint2 u1 = xb[(size_t)s1 * 32 + lane];
            uint2 u2 = xb[(size_t)s2 * 32 + lane];
            uint2 u3 = xb[(size_t)s3 * 32 + lane];
            acc_bf16w(a0, u0, w0);
            acc_bf16w(a1, u1, w1);
            acc_bf16w(a2, u2, w2);
            acc_bf16w(a3, u3, w3);
        }
        for (; j < m; j++) {
            int s0 = __shfl_sync(0xffffffffu, sl, j);
            float w0 = __shfl_sync(0xffffffffu, dl, j);
            uint2 u0 = xb[(size_t)s0 * 32 + lane];
            acc_bf16w(a0, u0, w0);
        }
    }

    float dv = g_dinv[v];
    uint2 us = xb[(size_t)v * 32 + lane];
    acc_bf16w(a0, us, dv);

    float4 b4 = ((const float4*)bias)[lane];
    float rx = dv * (a0.x + a1.x + a2.x + a3.x) + b4.x;
    float ry = dv * (a0.y + a1.y + a2.y + a3.y) + b4.y;
    float rz = dv * (a0.z + a1.z + a2.z + a3.z) + b4.z;
    float rw = dv * (a0.w + a1.w + a2.w + a3.w) + b4.w;

    if (do_relu) {
        rx = fmaxf(rx, 0.f); ry = fmaxf(ry, 0.f);
        rz = fmaxf(rz, 0.f); rw = fmaxf(rw, 0.f);
    }
    ((float4*)hout)[(size_t)v * 32 + lane] = make_float4(rx, ry, rz, rw);
}

// ---------------- Pool + MLP head ----------------
__global__ void pool_mlp_kernel(const float* __restrict__ h, const int* __restrict__ batch,
                                const float* __restrict__ w1, const float* __restrict__ b1,
                                const float* __restrict__ w2, const float* __restrict__ b2,
                                float* __restrict__ out) {
    int g = blockIdx.x;
    int t = threadIdx.x;

    __shared__ int s_bounds[2];
    if (t < 2) {
        int target = g + t;
        int lo = 0, hi = N_NODES;
        while (lo < hi) {
            int mid = (lo + hi) >> 1;
            if (batch[mid] < target) lo = mid + 1; else hi = mid;
        }
        s_bounds[t] = lo;
    }
    __syncthreads();
    int beg = s_bounds[0], end = s_bounds[1];

    float sum = 0.f;
    for (int n = beg; n < end; n++) sum += h[(size_t)n * D + t];
    float cnt = fmaxf((float)(end - beg), 1.0f);

    __shared__ float pooled[D];
    __shared__ float hid[100];
    pooled[t] = sum / cnt;
    __syncthreads();

    if (t < 100) {
        float a = b1[t];
        #pragma unroll 8
        for (int k = 0; k < D; k++) a += pooled[k] * w1[k * 100 + t];
        hid[t] = fmaxf(a, 0.f);
    }
    __syncthreads();

    if (t < 4) {
        float a = b2[t];
        #pragma unroll
        for (int k = 0; k < 100; k++) a += hid[k] * w2[k * 4 + t];
        out[g * 4 + t] = a;
    }
}

// ---------------- launch ----------------
extern "C" void kernel_launch(void* const* d_in, const int* in_sizes, int n_in,
                              void* d_out, int out_size) {
    const float *x = 0, *Ws = 0, *bs = 0, *w1 = 0, *b1 = 0, *w2 = 0, *b2 = 0;
    const int *eidx = 0, *batch = 0;
    for (int i = 0; i < n_in; i++) {
        switch (in_sizes[i]) {
            case 12800000: x     = (const float*)d_in[i]; break;
            case 65536:    Ws    = (const float*)d_in[i]; break;
            case 512:      bs    = (const float*)d_in[i]; break;
            case 12800:    w1    = (const float*)d_in[i]; break;
            case 100:      b1    = (const float*)d_in[i]; break;
            case 400:      w2    = (const float*)d_in[i]; break;
            case 4:        b2    = (const float*)d_in[i]; break;
            case 3200000:  eidx  = (const int*)d_in[i]; break;
            case 100000:   batch = (const int*)d_in[i]; break;
            default: break;
        }
    }
    float* out = (float*)d_out;

    const int* row = eidx;
    const int* col = eidx + N_EDGES;

    float *p_h = nullptr;
    __nv_bfloat16 *p_xwb = nullptr;
    uint4 *p_wpack = nullptr;
    cudaGetSymbolAddress((void**)&p_xwb,  g_xwb);
    cudaGetSymbolAddress((void**)&p_h,    g_h);
    cudaGetSymbolAddress((void**)&p_wpack, g_wpack);

    const int NB_NODE = (N_NODES + 255) / 256;
    const int NB_EDGE4 = (N_EDGES / 4 + 255) / 256;
    const int TC_BLOCKS = (N_NODES + 63) / 64;           // 1563
    const int AGG_BLOCKS = (N_NODES * 32 + 255) / 256;   // warp/node

    cudaFuncSetAttribute(gemm_mma_kernel, cudaFuncAttributeMaxDynamicSharedMemorySize, GEMM_SMEM);

    // Slot 3 carries an aggregate_kernel PROBE so ncu (-s 5 -c 1) profiles the
    // production aggregation kernel.  It reads CSR/xwb state persisted from the
    // previous launch (inputs are constant, so that state is identical to what
    // this launch rebuilds); its g_h output is fully overwritten by the real
    // layer-0 aggregation below, so d_out is unaffected.
    wsplit_kernel<<<N_LAYERS, 256>>>(Ws);                                   // [0]
    zero_cnt_kernel<<<NB_NODE, 256>>>();                                    // [1]
    count_kernel<<<NB_EDGE4, 256>>>((const int4*)col);                      // [2]
    aggregate_kernel<<<AGG_BLOCKS, 256>>>(p_xwb, bs, p_h, 1);               // [3] <- PROFILED probe
    gemm_mma_kernel<<<TC_BLOCKS, 256, GEMM_SMEM>>>(x, p_wpack, p_xwb);      // [4]
    scan1_kernel<<<NB_NODE, 256>>>();                                       // [5]
    scan2_kernel<<<1, 512>>>(NB_NODE);                                      // [6]
    scan3_kernel<<<NB_NODE, 256>>>();                                       // [7]
    fill_kernel<<<NB_EDGE4, 256>>>((const int4*)row, (const int4*)col);     // [8]

    aggregate_kernel<<<AGG_BLOCKS, 256>>>(p_xwb, bs, p_h, 1);               // real L0 agg
    const float* hin = p_h;
    for (int l = 1; l < N_LAYERS; l++) {
        gemm_mma_kernel<<<TC_BLOCKS, 256, GEMM_SMEM>>>(hin, p_wpack + (size_t)l * 4096, p_xwb);
        aggregate_kernel<<<AGG_BLOCKS, 256>>>(p_xwb, bs + (size_t)l * D, p_h,
                                              (l < N_LAYERS - 1) ? 1 : 0);
        hin = p_h;
    }

    pool_mlp_kernel<<<N_GRAPHS, 128>>>(p_h, batch, w1, b1, w2, b2, out);
}

// round 15
// speedup vs baseline: 1.9906x; 1.2906x over previous
#include <cuda_runtime.h>
#include <cuda_bf16.h>
#include <cstdint>

#define N_NODES 100000
#define N_EDGES 1600000
#define D 128
#define N_LAYERS 4
#define N_GRAPHS 512

// ---------------- device scratch ----------------
__device__ __nv_bfloat16 g_xwb[N_NODES * D];   // XW bf16 (25.6 MB)
__device__ __nv_bfloat16 g_hb[N_NODES * D];    // hidden bf16 (25.6 MB)
__device__ float g_dinv[N_NODES];
__device__ int   g_cnt[N_NODES];
__device__ int   g_rowptr[N_NODES + 1];
__device__ int   g_cursor[N_NODES];
__device__ int   g_bsum[512];
__device__ int   g_src[N_EDGES];
__device__ uint4 g_wpack[N_LAYERS * 4096];

// ---------------- CSR build ----------------
__global__ void zero_cnt_kernel() {
    int i = blockIdx.x * blockDim.x + threadIdx.x;
    if (i < N_NODES) g_cnt[i] = 0;
}

__device__ __forceinline__ int clampi(int v, int hi) {
    return v < 0 ? 0 : (v >= hi ? hi - 1 : v);
}

__global__ void count_kernel(const int4* __restrict__ col4) {
    int e = blockIdx.x * blockDim.x + threadIdx.x;
    if (e < N_EDGES / 4) {
        int4 c = col4[e];
        atomicAdd(&g_cnt[clampi(c.x, N_NODES)], 1);
        atomicAdd(&g_cnt[clampi(c.y, N_NODES)], 1);
        atomicAdd(&g_cnt[clampi(c.z, N_NODES)], 1);
        atomicAdd(&g_cnt[clampi(c.w, N_NODES)], 1);
    }
}

__global__ void scan1_kernel() {
    __shared__ int s[256];
    int t = threadIdx.x;
    int i = blockIdx.x * 256 + t;
    int v = (i < N_NODES) ? g_cnt[i] : 0;
    s[t] = v;
    __syncthreads();
    #pragma unroll
    for (int off = 1; off < 256; off <<= 1) {
        int add = (t >= off) ? s[t - off] : 0;
        __syncthreads();
        s[t] += add;
        __syncthreads();
    }
    if (i < N_NODES) g_rowptr[i] = s[t] - v;
    if (t == 255) g_bsum[blockIdx.x] = s[255];
}

__global__ void scan2_kernel(int nblocks) {
    __shared__ int s[512];
    int t = threadIdx.x;
    int v = (t < nblocks) ? g_bsum[t] : 0;
    s[t] = v;
    __syncthreads();
    #pragma unroll
    for (int off = 1; off < 512; off <<= 1) {
        int add = (t >= off) ? s[t - off] : 0;
        __syncthreads();
        s[t] += add;
        __syncthreads();
    }
    if (t < nblocks) g_bsum[t] = s[t] - v;
}

__global__ void scan3_kernel() {
    int i = blockIdx.x * 256 + threadIdx.x;
    if (i < N_NODES) {
        int rp = g_rowptr[i] + g_bsum[blockIdx.x];
        g_rowptr[i] = rp;
        g_cursor[i] = rp;
        g_dinv[i] = rsqrtf((float)(g_cnt[i] + 1));
    }
    if (i == 0) g_rowptr[N_NODES] = N_EDGES;
}

__global__ void fill_kernel(const int4* __restrict__ row4, const int4* __restrict__ col4) {
    int e = blockIdx.x * blockDim.x + threadIdx.x;
    if (e < N_EDGES / 4) {
        int4 r = row4[e];
        int4 c = col4[e];
        int p;
        p = atomicAdd(&g_cursor[clampi(c.x, N_NODES)], 1);
        if (p >= 0 && p < N_EDGES) g_src[p] = clampi(r.x, N_NODES);
        p = atomicAdd(&g_cursor[clampi(c.y, N_NODES)], 1);
        if (p >= 0 && p < N_EDGES) g_src[p] = clampi(r.y, N_NODES);
        p = atomicAdd(&g_cursor[clampi(c.z, N_NODES)], 1);
        if (p >= 0 && p < N_EDGES) g_src[p] = clampi(r.z, N_NODES);
        p = atomicAdd(&g_cursor[clampi(c.w, N_NODES)], 1);
        if (p >= 0 && p < N_EDGES) g_src[p] = clampi(r.w, N_NODES);
    }
}

// ---------------- W preprocessing ----------------
__device__ __forceinline__ uint32_t pack_bf16(float a, float b) {
    return (uint32_t)__bfloat16_as_ushort(__float2bfloat16_rn(a))
         | ((uint32_t)__bfloat16_as_ushort(__float2bfloat16_rn(b)) << 16);
}
__device__ __forceinline__ float bf16_res(float a) {
    return a - __bfloat162float(__float2bfloat16_rn(a));
}

__global__ void wsplit_kernel(const float* __restrict__ Ws) {
    int l = blockIdx.x;
    const float* W = Ws + l * D * D;
    for (int idx = threadIdx.x; idx < 4096; idx += blockDim.x) {
        int lane = idx & 31;
        int nt = (idx >> 5) & 15;
        int s = idx >> 9;
        int g = lane >> 2, tg = lane & 3;
        int n = nt * 8 + g;
        int ka = s * 16 + tg * 2;
        int kb = ka + 8;
        float w00 = W[ka * D + n], w01 = W[(ka + 1) * D + n];
        float w10 = W[kb * D + n], w11 = W[(kb + 1) * D + n];
        uint4 o;
        o.x = pack_bf16(w00, w01);
        o.y = pack_bf16(w10, w11);
        o.z = pack_bf16(bf16_res(w00), bf16_res(w01));
        o.w = pack_bf16(bf16_res(w10), bf16_res(w11));
        g_wpack[l * 4096 + idx] = o;
    }
}

// ---------------- GEMM helpers ----------------
#define FRAG_STRIDE 528

__device__ __forceinline__ void mma16816(float c[4], uint32_t a0, uint32_t a1, uint32_t a2,
                                         uint32_t a3, uint32_t b0, uint32_t b1) {
    asm volatile(
        "mma.sync.aligned.m16n8k16.row.col.f32.bf16.bf16.f32 "
        "{%0,%1,%2,%3}, {%4,%5,%6,%7}, {%8,%9}, {%0,%1,%2,%3};"
        : "+f"(c[0]), "+f"(c[1]), "+f"(c[2]), "+f"(c[3])
        : "r"(a0), "r"(a1), "r"(a2), "r"(a3), "r"(b0), "r"(b1));
}

// ---- Layer-0 GEMM: fp32 A, split hi/lo, 3 products ----
#define SM_AHI 0
#define SM_ALO (SM_AHI + 32 * FRAG_STRIDE)
#define GEMM_SMEM (SM_ALO + 32 * FRAG_STRIDE)  // 33792

__global__ void __launch_bounds__(256, 2)
gemm_mma_kernel(const float* __restrict__ A,
                const uint4* __restrict__ wpack,
                __nv_bfloat16* __restrict__ Cb) {
    extern __shared__ char smem[];
    int t = threadIdx.x;
    int warp = t >> 5, lane = t & 31;
    int m0 = blockIdx.x * 64;

    {
        const float4* A4 = (const float4*)A;
        #pragma unroll
        for (int i = 0; i < 8; i++) {
            int idx = i * 256 + t;
            int row = idx >> 5, q = idx & 31;
            float4 v = make_float4(0.f, 0.f, 0.f, 0.f);
            if (m0 + row < N_NODES) v = A4[(size_t)(m0 + row) * 32 + q];
            int rowin = row & 15, wb = row >> 4;
            int g = rowin & 7, hr = rowin >> 3;
            int s = q >> 2, rr = (q & 3) << 2;
            int tg0 = (rr & 4) ? 2 : 0;
            int sl = ((rr & 8) ? 2 : 0) + hr;
            int l0 = (g << 2) + tg0;
            int foff = (wb * 8 + s) * FRAG_STRIDE;
            *(uint32_t*)(smem + SM_AHI + foff + l0 * 16 + sl * 4) = pack_bf16(v.x, v.y);
            *(uint32_t*)(smem + SM_AHI + foff + (l0 + 1) * 16 + sl * 4) = pack_bf16(v.z, v.w);
            *(uint32_t*)(smem + SM_ALO + foff + l0 * 16 + sl * 4) =
                pack_bf16(bf16_res(v.x), bf16_res(v.y));
            *(uint32_t*)(smem + SM_ALO + foff + (l0 + 1) * 16 + sl * 4) =
                pack_bf16(bf16_res(v.z), bf16_res(v.w));
        }
    }
    __syncthreads();

    int rowblk = warp >> 1;
    int nthalf = warp & 1;
    int g = lane >> 2;
    int tg = lane & 3;

    float acc[8][4];
    #pragma unroll
    for (int nt = 0; nt < 8; nt++)
        #pragma unroll
        for (int j = 0; j < 4; j++) acc[nt][j] = 0.f;

    #pragma unroll
    for (int s = 0; s < 8; s++) {
        int foff = (rowblk * 8 + s) * FRAG_STRIDE + lane * 16;
        uint4 ha = *(const uint4*)(smem + SM_AHI + foff);
        uint4 la = *(const uint4*)(smem + SM_ALO + foff);
        const uint4* bp = wpack + s * 512 + (nthalf * 8) * 32 + lane;
        #pragma unroll
        for (int nt = 0; nt < 8; nt++) {
            uint4 bb = __ldg(bp + nt * 32);
            mma16816(acc[nt], ha.x, ha.y, ha.z, ha.w, bb.x, bb.y);
            mma16816(acc[nt], ha.x, ha.y, ha.z, ha.w, bb.z, bb.w);
            mma16816(acc[nt], la.x, la.y, la.z, la.w, bb.x, bb.y);
        }
    }

    int r0 = m0 + rowblk * 16 + g;
    int r1 = r0 + 8;
    #pragma unroll
    for (int nt = 0; nt < 8; nt++) {
        int cb = (nthalf * 8 + nt) * 8 + tg * 2;
        if (r0 < N_NODES)
            *(uint32_t*)&Cb[(size_t)r0 * D + cb] = pack_bf16(acc[nt][0], acc[nt][1]);
        if (r1 < N_NODES)
            *(uint32_t*)&Cb[(size_t)r1 * D + cb] = pack_bf16(acc[nt][2], acc[nt][3]);
    }
}

// ---- Layers 1-3 GEMM: bf16 A (exact), 2 products, half smem ----
#define GEMMB_SMEM (32 * FRAG_STRIDE)          // 16896

__global__ void __launch_bounds__(256, 2)
gemm_bf16_kernel(const __nv_bfloat16* __restrict__ A,
                 const uint4* __restrict__ wpack,
                 __nv_bfloat16* __restrict__ Cb) {
    extern __shared__ char smem[];
    int t = threadIdx.x;
    int warp = t >> 5, lane = t & 31;
    int m0 = blockIdx.x * 64;

    // A tile: 64 rows x 64 u32 (bf16x2).  uint2 loads (2 u32 = 4 cols each).
    {
        const uint2* A2 = (const uint2*)A;     // 32 uint2 per row
        #pragma unroll
        for (int i = 0; i < 8; i++) {
            int idx = i * 256 + t;             // 2048 uint2 slots
            int row = idx >> 5, c2 = idx & 31; // c2: uint2 index, covers u32 c=2*c2, 2*c2+1
            uint2 v = make_uint2(0u, 0u);
            if (m0 + row < N_NODES) v = A2[(size_t)(m0 + row) * 32 + c2];
            int rowin = row & 15, wb = row >> 4;
            int g = rowin & 7, hr = rowin >> 3;
            int c = c2 * 2;                    // even u32 index
            int s = c >> 3;
            int tg = c & 3;                    // tg for u32 c; c+1 -> tg+1
            int sl = ((c & 4) ? 2 : 0) + hr;
            int l0 = (g << 2) + tg;
            int foff = (wb * 8 + s) * FRAG_STRIDE;
            *(uint32_t*)(smem + foff + l0 * 16 + sl * 4) = v.x;
            *(uint32_t*)(smem + foff + (l0 + 1) * 16 + sl * 4) = v.y;
        }
    }
    __syncthreads();

    int rowblk = warp >> 1;
    int nthalf = warp & 1;
    int g = lane >> 2;
    int tg = lane & 3;

    float acc[8][4];
    #pragma unroll
    for (int nt = 0; nt < 8; nt++)
        #pragma unroll
        for (int j = 0; j < 4; j++) acc[nt][j] = 0.f;

    #pragma unroll
    for (int s = 0; s < 8; s++) {
        int foff = (rowblk * 8 + s) * FRAG_STRIDE + lane * 16;
        uint4 ha = *(const uint4*)(smem + foff);
        const uint4* bp = wpack + s * 512 + (nthalf * 8) * 32 + lane;
        #pragma unroll
        for (int nt = 0; nt < 8; nt++) {
            uint4 bb = __ldg(bp + nt * 32);
            mma16816(acc[nt], ha.x, ha.y, ha.z, ha.w, bb.x, bb.y);   // A * Whi
            mma16816(acc[nt], ha.x, ha.y, ha.z, ha.w, bb.z, bb.w);   // A * Wlo
        }
    }

    int r0 = m0 + rowblk * 16 + g;
    int r1 = r0 + 8;
    #pragma unroll
    for (int nt = 0; nt < 8; nt++) {
        int cb = (nthalf * 8 + nt) * 8 + tg * 2;
        if (r0 < N_NODES)
            *(uint32_t*)&Cb[(size_t)r0 * D + cb] = pack_bf16(acc[nt][0], acc[nt][1]);
        if (r1 < N_NODES)
            *(uint32_t*)&Cb[(size_t)r1 * D + cb] = pack_bf16(acc[nt][2], acc[nt][3]);
    }
}

// ---------------- Aggregation (warp/node, bf16 in + bf16 out) ----------------
__device__ __forceinline__ void acc_bf16w(float4& a, uint2 u, float w) {
    float f0 = __uint_as_float(u.x << 16);
    float f1 = __uint_as_float(u.x & 0xffff0000u);
    float f2 = __uint_as_float(u.y << 16);
    float f3 = __uint_as_float(u.y & 0xffff0000u);
    a.x = fmaf(w, f0, a.x); a.y = fmaf(w, f1, a.y);
    a.z = fmaf(w, f2, a.z); a.w = fmaf(w, f3, a.w);
}

__global__ void aggregate_kernel(const __nv_bfloat16* __restrict__ xwb,
                                 const float* __restrict__ bias,
                                 __nv_bfloat16* __restrict__ hout, int do_relu) {
    int gw = (blockIdx.x * blockDim.x + threadIdx.x) >> 5;
    int lane = threadIdx.x & 31;
    if (gw >= N_NODES) return;
    int v = gw;
    int beg = g_rowptr[v];
    int end = g_rowptr[v + 1];

    const uint2* xb = (const uint2*)xwb;
    float4 a0 = make_float4(0.f, 0.f, 0.f, 0.f);
    float4 a1 = make_float4(0.f, 0.f, 0.f, 0.f);
    float4 a2 = make_float4(0.f, 0.f, 0.f, 0.f);
    float4 a3 = make_float4(0.f, 0.f, 0.f, 0.f);

    for (int p = beg; p < end; p += 32) {
        int m = end - p; if (m > 32) m = 32;
        int sl = g_src[p + (lane < m ? lane : 0)];
        float dl = g_dinv[sl];
        int j = 0;
        for (; j + 4 <= m; j += 4) {
            int s0 = __shfl_sync(0xffffffffu, sl, j);
            int s1 = __shfl_sync(0xffffffffu, sl, j + 1);
            int s2 = __shfl_sync(0xffffffffu, sl, j + 2);
            int s3 = __shfl_sync(0xffffffffu, sl, j + 3);
            float w0 = __shfl_sync(0xffffffffu, dl, j);
            float w1 = __shfl_sync(0xffffffffu, dl, j + 1);
            float w2 = __shfl_sync(0xffffffffu, dl, j + 2);
            float w3 = __shfl_sync(0xffffffffu, dl, j + 3);
            uint2 u0 = xb[(size_t)s0 * 32 + lane];
            uint2 u1 = xb[(size_t)s1 * 32 + lane];
            uint2 u2 = xb[(size_t)s2 * 32 + lane];
            uint2 u3 = xb[(size_t)s3 * 32 + lane];
            acc_bf16w(a0, u0, w0);
            acc_bf16w(a1, u1, w1);
            acc_bf16w(a2, u2, w2);
            acc_bf16w(a3, u3, w3);
        }
        for (; j < m; j++) {
            int s0 = __shfl_sync(0xffffffffu, sl, j);
            float w0 = __shfl_sync(0xffffffffu, dl, j);
            uint2 u0 = xb[(size_t)s0 * 32 + lane];
            acc_bf16w(a0, u0, w0);
        }
    }

    float dv = g_dinv[v];
    uint2 us = xb[(size_t)v * 32 + lane];
    acc_bf16w(a0, us, dv);

    float4 b4 = ((const float4*)bias)[lane];
    float rx = dv * (a0.x + a1.x + a2.x + a3.x) + b4.x;
    float ry = dv * (a0.y + a1.y + a2.y + a3.y) + b4.y;
    float rz = dv * (a0.z + a1.z + a2.z + a3.z) + b4.z;
    float rw = dv * (a0.w + a1.w + a2.w + a3.w) + b4.w;

    if (do_relu) {
        rx = fmaxf(rx, 0.f); ry = fmaxf(ry, 0.f);
        rz = fmaxf(rz, 0.f); rw = fmaxf(rw, 0.f);
    }
    uint2 pk = make_uint2(pack_bf16(rx, ry), pack_bf16(rz, rw));
    ((uint2*)hout)[(size_t)v * 32 + lane] = pk;
}

// ---------------- Pool + MLP head (bf16 h input) ----------------
__global__ void pool_mlp_kernel(const __nv_bfloat16* __restrict__ h,
                                const int* __restrict__ batch,
                                const float* __restrict__ w1, const float* __restrict__ b1,
                                const float* __restrict__ w2, const float* __restrict__ b2,
                                float* __restrict__ out) {
    int g = blockIdx.x;
    int t = threadIdx.x;

    __shared__ int s_bounds[2];
    if (t < 2) {
        int target = g + t;
        int lo = 0, hi = N_NODES;
        while (lo < hi) {
            int mid = (lo + hi) >> 1;
            if (batch[mid] < target) lo = mid + 1; else hi = mid;
        }
        s_bounds[t] = lo;
    }
    __syncthreads();
    int beg = s_bounds[0], end = s_bounds[1];

    float sum = 0.f;
    for (int n = beg; n < end; n++)
        sum += __bfloat162float(h[(size_t)n * D + t]);
    float cnt = fmaxf((float)(end - beg), 1.0f);

    __shared__ float pooled[D];
    __shared__ float hid[100];
    pooled[t] = sum / cnt;
    __syncthreads();

    if (t < 100) {
        float a = b1[t];
        #pragma unroll 8
        for (int k = 0; k < D; k++) a += pooled[k] * w1[k * 100 + t];
        hid[t] = fmaxf(a, 0.f);
    }
    __syncthreads();

    if (t < 4) {
        float a = b2[t];
        #pragma unroll
        for (int k = 0; k < 100; k++) a += hid[k] * w2[k * 4 + t];
        out[g * 4 + t] = a;
    }
}

// ---------------- launch ----------------
extern "C" void kernel_launch(void* const* d_in, const int* in_sizes, int n_in,
                              void* d_out, int out_size) {
    const float *x = 0, *Ws = 0, *bs = 0, *w1 = 0, *b1 = 0, *w2 = 0, *b2 = 0;
    const int *eidx = 0, *batch = 0;
    for (int i = 0; i < n_in; i++) {
        switch (in_sizes[i]) {
            case 12800000: x     = (const float*)d_in[i]; break;
            case 65536:    Ws    = (const float*)d_in[i]; break;
            case 512:      bs    = (const float*)d_in[i]; break;
            case 12800:    w1    = (const float*)d_in[i]; break;
            case 100:      b1    = (const float*)d_in[i]; break;
            case 400:      w2    = (const float*)d_in[i]; break;
            case 4:        b2    = (const float*)d_in[i]; break;
            case 3200000:  eidx  = (const int*)d_in[i]; break;
            case 100000:   batch = (const int*)d_in[i]; break;
            default: break;
        }
    }
    float* out = (float*)d_out;

    const int* row = eidx;
    const int* col = eidx + N_EDGES;

    __nv_bfloat16 *p_xwb = nullptr, *p_hb = nullptr;
    uint4 *p_wpack = nullptr;
    cudaGetSymbolAddress((void**)&p_xwb,  g_xwb);
    cudaGetSymbolAddress((void**)&p_hb,   g_hb);
    cudaGetSymbolAddress((void**)&p_wpack, g_wpack);

    const int NB_NODE = (N_NODES + 255) / 256;
    const int NB_EDGE4 = (N_EDGES / 4 + 255) / 256;
    const int TC_BLOCKS = (N_NODES + 63) / 64;           // 1563
    const int AGG_BLOCKS = (N_NODES * 32 + 255) / 256;   // warp/node

    cudaFuncSetAttribute(gemm_mma_kernel, cudaFuncAttributeMaxDynamicSharedMemorySize, GEMM_SMEM);

    // Slot 3 = count_kernel (profiled by ncu -s 5 -c 1): first direct look at
    // the CSR atomic build cost.
    wsplit_kernel<<<N_LAYERS, 256>>>(Ws);                                   // [0]
    zero_cnt_kernel<<<NB_NODE, 256>>>();                                    // [1]
    gemm_mma_kernel<<<TC_BLOCKS, 256, GEMM_SMEM>>>(x, p_wpack, p_xwb);      // [2] L0 GEMM
    count_kernel<<<NB_EDGE4, 256>>>((const int4*)col);                      // [3] <- PROFILED
    scan1_kernel<<<NB_NODE, 256>>>();                                       // [4]
    scan2_kernel<<<1, 512>>>(NB_NODE);                                      // [5]
    scan3_kernel<<<NB_NODE, 256>>>();                                       // [6]
    fill_kernel<<<NB_EDGE4, 256>>>((const int4*)row, (const int4*)col);     // [7]

    aggregate_kernel<<<AGG_BLOCKS, 256>>>(p_xwb, bs, p_hb, 1);              // L0 agg
    for (int l = 1; l < N_LAYERS; l++) {
        gemm_bf16_kernel<<<TC_BLOCKS, 256, GEMMB_SMEM>>>(p_hb, p_wpack + (size_t)l * 4096, p_xwb);
        aggregate_kernel<<<AGG_BLOCKS, 256>>>(p_xwb, bs + (size_t)l * D, p_hb,
                                              (l < N_LAYERS - 1) ? 1 : 0);
    }

    pool_mlp_kernel<<<N_GRAPHS, 128>>>(p_hb, batch, w1, b1, w2, b2, out);
}